// round 7
// baseline (speedup 1.0000x reference)
#include <cuda_runtime.h>
#include <math.h>

// Problem constants
constexpr int BB  = 1024;
constexpr int NN  = 200;
constexpr int DNC = 128;   // DN
constexpr int DTC = 128;   // DT
constexpr int MM  = 384;   // DN + DN + DT
constexpr int G   = 8;     // batches per CTA in MLP kernel
constexpr int TT  = 24;    // rows per attention tile (2 per warp, 12 warps)
constexpr int NTI = 9;     // ceil(200/24); last tile has 8 rows

// padded smem strides (words), 16B-aligned
constexpr int SQ = 388;
constexpr int SX = 516;
constexpr int SH = 260;

// Scratch: attention output vectors ov[b][m] (pre-FC)
__device__ float g_ov[BB * MM];
// Transposed weights (written by transpose3_kernel each launch)
__device__ float g_fcwT[MM * MM];        // [k][j], 384x384
__device__ float g_w1T [512 * 256];      // [k][j], k<512, j<256
__device__ float g_w2T [256 * 128];      // [k][j], k<256, j<128

__device__ __forceinline__ float dot4(float4 a, float4 b) {
    return a.x*b.x + a.y*b.y + a.z*b.z + a.w*b.w;
}

// ---------------------------------------------------------------------------
// Kernel 0: transpose fc_w / w1 / w2 into __device__ scratch.
// 32x32 tiles, block (32,8). All dims divisible by 32.
//   tiles: fc_w 12x12=144, w1 8x16=128, w2 4x8=32  -> 304 blocks
// ---------------------------------------------------------------------------
__global__ void transpose3_kernel(const float* __restrict__ fc_w,
                                  const float* __restrict__ w1,
                                  const float* __restrict__ w2)
{
    __shared__ float tile[32][33];
    int bid = blockIdx.x;
    const float* in; float* out; int R, C, tid, tk_count;
    if (bid < 144)      { in = fc_w; out = g_fcwT; R = 384; C = 384; tid = bid;       tk_count = 12; }
    else if (bid < 272) { in = w1;   out = g_w1T;  R = 256; C = 512; tid = bid - 144; tk_count = 16; }
    else                { in = w2;   out = g_w2T;  R = 128; C = 256; tid = bid - 272; tk_count = 8;  }
    const int tile_r = tid / tk_count;   // row-tile of input
    const int tile_k = tid % tk_count;   // col-tile of input
    const int tx = threadIdx.x, ty = threadIdx.y;
    #pragma unroll
    for (int i = ty; i < 32; i += 8)
        tile[i][tx] = in[(size_t)(tile_r * 32 + i) * C + tile_k * 32 + tx];
    __syncthreads();
    #pragma unroll
    for (int i = ty; i < 32; i += 8)
        out[(size_t)(tile_k * 32 + i) * R + tile_r * 32 + tx] = tile[tx][i];
}

// ---------------------------------------------------------------------------
// Kernel 1: fused single-pass attention, shift-free softmax. (unchanged, R5)
// ---------------------------------------------------------------------------
__global__ __launch_bounds__(384, 3) void attn_kernel(
    const float* __restrict__ seq,
    const float* __restrict__ seq_e,
    const float* __restrict__ seq_t,
    const void* __restrict__ mask,
    const float* __restrict__ shared_attn,
    float* __restrict__ out_attn)   // = d_out + B*DN
{
    __shared__ __align__(16) float s_wk[MM];
    __shared__ __align__(16) float s_k[TT][MM];
    __shared__ float s_e[NN];
    __shared__ float s_sum;
    __shared__ int   s_det[2];
    __shared__ unsigned char s_msk[NN];

    const int b = blockIdx.x;
    const int t = threadIdx.x;
    const int w = t >> 5;
    const int l = t & 31;
    const size_t rowbase = (size_t)b * NN;

    s_wk[t] = shared_attn[MM + t];
    if (t < 64) {
        unsigned int v = ((const unsigned int*)mask)[t];
        unsigned int bad = __ballot_sync(0xffffffffu, v > 1u);
        if (l == 0) s_det[w] = (bad != 0u);
    }
    __syncthreads();

    const bool mask_is_int = !(s_det[0] | s_det[1]);
    if (t < NN) {
        bool m = mask_is_int
            ? (((const int*)mask)[rowbase + t] != 0)
            : (((const unsigned char*)mask)[rowbase + t] != 0);
        s_msk[t] = m ? 1 : 0;
    }

    float4 wa = ((const float4*)s_wk)[l];
    float4 we = ((const float4*)s_wk)[32 + l];
    float4 wc = ((const float4*)s_wk)[64 + l];
    __syncthreads();

    const float4* seq4  = (const float4*)seq;
    const float4* seqe4 = (const float4*)seq_e;
    const float4* seqt4 = (const float4*)seq_t;

    float4 A0, E0, C0, A1, E1, C1;
    const int r0 = 2 * w, r1 = 2 * w + 1;
    {
        size_t o = (rowbase + r0) * 32 + l;
        A0 = seq4[o]; E0 = seqe4[o]; C0 = seqt4[o];
        o = (rowbase + r1) * 32 + l;
        A1 = seq4[o]; E1 = seqe4[o]; C1 = seqt4[o];
    }

    float acc = 0.0f;

    for (int tt = 0; tt < NTI; tt++) {
        const int n0 = tt * TT;
        const int Tc = (tt == NTI - 1) ? (NN - (NTI - 1) * TT) : TT;

        if (r0 < Tc) {
            float p = dot4(A0, wa) + dot4(E0, we) + dot4(C0, wc);
            #pragma unroll
            for (int o = 16; o; o >>= 1) p += __shfl_xor_sync(0xffffffffu, p, o);
            if (l == 0) s_e[n0 + r0] = s_msk[n0 + r0] ? 0.0f : __expf(p - 8.0f);
            float4* row = (float4*)s_k[r0];
            row[l] = A0; row[32 + l] = E0; row[64 + l] = C0;
        }
        if (r1 < Tc) {
            float p = dot4(A1, wa) + dot4(E1, we) + dot4(C1, wc);
            #pragma unroll
            for (int o = 16; o; o >>= 1) p += __shfl_xor_sync(0xffffffffu, p, o);
            if (l == 0) s_e[n0 + r1] = s_msk[n0 + r1] ? 0.0f : __expf(p - 8.0f);
            float4* row = (float4*)s_k[r1];
            row[l] = A1; row[32 + l] = E1; row[64 + l] = C1;
        }

        if (tt + 1 < NTI) {
            const int m0 = (tt + 1) * TT;
            int n = m0 + r0;
            if (n < NN) {
                size_t o = (rowbase + n) * 32 + l;
                A0 = seq4[o]; E0 = seqe4[o]; C0 = seqt4[o];
            }
            n = m0 + r1;
            if (n < NN) {
                size_t o = (rowbase + n) * 32 + l;
                A1 = seq4[o]; E1 = seqe4[o]; C1 = seqt4[o];
            }
        }
        __syncthreads();

        float a = acc;
        if (Tc == TT) {
            #pragma unroll
            for (int i = 0; i < TT; i++) a = fmaf(s_e[n0 + i], s_k[i][t], a);
        } else {
            #pragma unroll
            for (int i = 0; i < 8; i++) a = fmaf(s_e[n0 + i], s_k[i][t], a);
        }
        acc = a;
        __syncthreads();
    }

    if (w == 0) {
        float s = 0.0f;
        #pragma unroll
        for (int k = l; k < NN; k += 32) s += s_e[k];
        #pragma unroll
        for (int o = 16; o; o >>= 1) s += __shfl_xor_sync(0xffffffffu, s, o);
        if (l == 0) s_sum = s;
    }
    __syncthreads();
    const float inv = 1.0f / s_sum;
    if (t < NN) out_attn[rowbase + t] = s_e[t] * inv;
    g_ov[(size_t)b * MM + t] = acc * inv;
}

// ---------------------------------------------------------------------------
// Outer-product matvec core: thread owns 2 batch rows x 4 output columns.
// wT is [K][JQV*4] transposed weights; x0p/x1p are smem rows (broadcast LDS).
// Double-buffered 8-k weight chunks (wA/wB) to hide L2 latency. Zero shuffles.
// ---------------------------------------------------------------------------
__device__ __forceinline__ void fma8(float4& a0, float4& a1,
                                     const float4 w[8],
                                     const float* xs0, const float* xs1) {
    #pragma unroll
    for (int i = 0; i < 8; i++) {
        float x0 = xs0[i], x1 = xs1[i];
        a0.x = fmaf(w[i].x, x0, a0.x); a0.y = fmaf(w[i].y, x0, a0.y);
        a0.z = fmaf(w[i].z, x0, a0.z); a0.w = fmaf(w[i].w, x0, a0.w);
        a1.x = fmaf(w[i].x, x1, a1.x); a1.y = fmaf(w[i].y, x1, a1.y);
        a1.z = fmaf(w[i].z, x1, a1.z); a1.w = fmaf(w[i].w, x1, a1.w);
    }
}

template<int K, int JQV>
__device__ __forceinline__ void mv2(const float4* __restrict__ wT,
                                    const float* __restrict__ x0p,
                                    const float* __restrict__ x1p,
                                    int jq, float4& a0, float4& a1) {
    float4 wA[8], wB[8];
    #pragma unroll
    for (int i = 0; i < 8; i++) wA[i] = wT[(size_t)i * JQV + jq];
    a0 = make_float4(0.f, 0.f, 0.f, 0.f);
    a1 = make_float4(0.f, 0.f, 0.f, 0.f);
    for (int k = 0; k < K; k += 16) {
        #pragma unroll
        for (int i = 0; i < 8; i++) wB[i] = wT[(size_t)(k + 8 + i) * JQV + jq];
        float4 xa[2], xb[2];
        xa[0] = *(const float4*)(x0p + k);     xa[1] = *(const float4*)(x0p + k + 4);
        xb[0] = *(const float4*)(x1p + k);     xb[1] = *(const float4*)(x1p + k + 4);
        fma8(a0, a1, wA, (const float*)xa, (const float*)xb);
        if (k + 16 < K) {
            #pragma unroll
            for (int i = 0; i < 8; i++) wA[i] = wT[(size_t)(k + 16 + i) * JQV + jq];
        }
        xa[0] = *(const float4*)(x0p + k + 8); xa[1] = *(const float4*)(x0p + k + 12);
        xb[0] = *(const float4*)(x1p + k + 8); xb[1] = *(const float4*)(x1p + k + 12);
        fma8(a0, a1, wB, (const float*)xa, (const float*)xb);
    }
}

// ---------------------------------------------------------------------------
// Kernel 2: FC + LN(residual q) + 2-layer MLP, outer-product formulation.
// G=8 batches per CTA (grid = 128), 384 threads.
// Stage 1: thread (gg, jq): gg=t/96 -> batches {2gg,2gg+1}, jq=t%96 -> cols 4jq..
// Stage 3: t<256, gg=t/64, jq=t%64; Stage 4: t<128, gg=t/32, jq=t%32.
// Per-warp gg is uniform -> x LDS are broadcasts; w LDG coalesced over jq.
// ---------------------------------------------------------------------------
__global__ __launch_bounds__(384) void mlp_kernel(
    const float* __restrict__ src,
    const float* __restrict__ src_t,
    const float* __restrict__ ln_g,
    const float* __restrict__ ln_b,
    float* __restrict__ out)        // (B, 128)
{
    __shared__ __align__(16) float s_ov[G][MM];
    __shared__ __align__(16) float s_q [G][SQ];
    __shared__ __align__(16) float s_x [G][SX];
    __shared__ __align__(16) float s_h [G][SH];

    const int b0 = blockIdx.x * G;
    const int t  = threadIdx.x;
    const int w  = t >> 5;
    const int l  = t & 31;

    // ---- Stage 0: load ov, q, and src tail of x ----
    for (int i = t; i < G * MM; i += 384) {
        int g = i / MM, j = i - g * MM;
        s_ov[g][j] = g_ov[(size_t)b0 * MM + i];
        float qv;
        if (j < DNC)          qv = src[(size_t)(b0 + g) * DNC + j];
        else if (j < 2 * DNC) qv = 0.0f;
        else                  qv = src_t[(size_t)(b0 + g) * DTC + (j - 2 * DNC)];
        s_q[g][j] = qv;
    }
    for (int i = t; i < G * DNC; i += 384) {
        int g = i >> 7, j = i & 127;
        s_x[g][MM + j] = src[(size_t)(b0 + g) * DNC + j];
    }
    __syncthreads();

    // ---- Stage 1: y = ov @ fc_w.T + q  (384 cols; 96 quads x 4 ggroups) ----
    {
        const int gg = t / 96;          // 0..3
        const int jq = t - gg * 96;     // 0..95
        const int g0 = 2 * gg, g1 = g0 + 1;
        float4 a0, a1;
        mv2<MM, 96>((const float4*)g_fcwT, s_ov[g0], s_ov[g1], jq, a0, a1);
        const int j = 4 * jq;
        float4 q0 = *(const float4*)&s_q[g0][j];
        float4 q1 = *(const float4*)&s_q[g1][j];
        a0.x += q0.x; a0.y += q0.y; a0.z += q0.z; a0.w += q0.w;
        a1.x += q1.x; a1.y += q1.y; a1.z += q1.z; a1.w += q1.w;
        *(float4*)&s_x[g0][j] = a0;
        *(float4*)&s_x[g1][j] = a1;
    }
    __syncthreads();

    // ---- Stage 2: LayerNorm per batch row (warps 0..7, warp g = batch g) ----
    if (w < G) {
        const int g = w;
        float vals[12];
        float smu = 0.0f;
        #pragma unroll
        for (int i = 0; i < 12; i++) { float x = s_x[g][l + 32*i]; vals[i] = x; smu += x; }
        #pragma unroll
        for (int o = 16; o; o >>= 1) smu += __shfl_xor_sync(0xffffffffu, smu, o);
        float mu = smu * (1.0f / MM);
        float sq = 0.0f;
        #pragma unroll
        for (int i = 0; i < 12; i++) { float d = vals[i] - mu; sq += d * d; }
        #pragma unroll
        for (int o = 16; o; o >>= 1) sq += __shfl_xor_sync(0xffffffffu, sq, o);
        float rstd = rsqrtf(sq * (1.0f / MM) + 1e-5f);
        #pragma unroll
        for (int i = 0; i < 12; i++) {
            int j = l + 32*i;
            s_x[g][j] = (vals[i] - mu) * rstd * ln_g[j] + ln_b[j];
        }
    }
    __syncthreads();

    // ---- Stage 3: h = relu(x @ w1.T)  (256 cols; 64 quads x 4 ggroups) ----
    if (t < 256) {
        const int gg = t >> 6;          // 0..3
        const int jq = t & 63;          // 0..63
        const int g0 = 2 * gg, g1 = g0 + 1;
        float4 a0, a1;
        mv2<512, 64>((const float4*)g_w1T, s_x[g0], s_x[g1], jq, a0, a1);
        const int j = 4 * jq;
        a0.x = fmaxf(a0.x, 0.f); a0.y = fmaxf(a0.y, 0.f);
        a0.z = fmaxf(a0.z, 0.f); a0.w = fmaxf(a0.w, 0.f);
        a1.x = fmaxf(a1.x, 0.f); a1.y = fmaxf(a1.y, 0.f);
        a1.z = fmaxf(a1.z, 0.f); a1.w = fmaxf(a1.w, 0.f);
        *(float4*)&s_h[g0][j] = a0;
        *(float4*)&s_h[g1][j] = a1;
    }
    __syncthreads();

    // ---- Stage 4: o = h @ w2.T  (128 cols; 32 quads x 4 ggroups) -> global ----
    if (t < 128) {
        const int gg = t >> 5;          // 0..3
        const int jq = t & 31;          // 0..31
        const int g0 = 2 * gg, g1 = g0 + 1;
        float4 a0, a1;
        mv2<256, 32>((const float4*)g_w2T, s_h[g0], s_h[g1], jq, a0, a1);
        const int j = 4 * jq;
        *(float4*)(out + (size_t)(b0 + g0) * DNC + j) = a0;
        *(float4*)(out + (size_t)(b0 + g1) * DNC + j) = a1;
    }
}

// ---------------------------------------------------------------------------
// Input order (setup_inputs dict order):
//   0 src (B,DN) f32          1 src_t (B,1,DT) f32      2 seq (B,N,DN) f32
//   3 seq_t (B,N,DT) f32      4 seq_e (B,N,DN) f32      5 mask (B,N) bool/int
//   6 shared_attn (1,2M) f32  7 fc_w (M,M) f32          8 ln_g (M,) f32
//   9 ln_b (M,) f32          10 agg_fc_w1 (256,512)    11 agg_fc_w2 (128,256)
// Output: out (B,128) then attn_w (B,200), concatenated f32.
// ---------------------------------------------------------------------------
extern "C" void kernel_launch(void* const* d_in, const int* in_sizes, int n_in,
                              void* d_out, int out_size) {
    const float* src         = (const float*)d_in[0];
    const float* src_t       = (const float*)d_in[1];
    const float* seq         = (const float*)d_in[2];
    const float* seq_t       = (const float*)d_in[3];
    const float* seq_e       = (const float*)d_in[4];
    const void*  msk         = d_in[5];
    const float* shared_attn = (const float*)d_in[6];
    const float* fc_w        = (const float*)d_in[7];
    const float* ln_g        = (const float*)d_in[8];
    const float* ln_b        = (const float*)d_in[9];
    const float* w1          = (const float*)d_in[10];
    const float* w2          = (const float*)d_in[11];
    float* out = (float*)d_out;

    transpose3_kernel<<<304, dim3(32, 8)>>>(fc_w, w1, w2);
    attn_kernel<<<BB, 384>>>(seq, seq_e, seq_t, msk, shared_attn,
                             out + (size_t)BB * DNC);
    mlp_kernel<<<BB / G, 384>>>(src, src_t, ln_g, ln_b, out);
}

// round 8
// speedup vs baseline: 1.6240x; 1.6240x over previous
#include <cuda_runtime.h>
#include <math.h>

// Problem constants
constexpr int BB  = 1024;
constexpr int NN  = 200;
constexpr int KH  = 100;   // keys per split CTA
constexpr int DNC = 128;   // DN
constexpr int DTC = 128;   // DT
constexpr int MM  = 384;   // DN + DN + DT
constexpr int G   = 8;     // batches per CTA in MLP kernel
constexpr int TT  = 24;    // rows per attention tile (2 per warp, 12 warps)
constexpr int NTI = 5;     // ceil(100/24); last tile has 4 rows

// padded smem strides (words) for conflict-free lane-scatter stores
constexpr int SQ = 388;    // s_q stride
constexpr int SX = 516;    // s_x stride
constexpr int SH = 260;    // s_h stride

// Scratch: split-K partial attention outputs and exp-sums
__device__ float g_ovp[2 * BB * MM];   // [b][split][m], unnormalized
__device__ float g_psum[2 * BB];       // [b][split] exp-sums

__device__ __forceinline__ float dot4(float4 a, float4 b) {
    return a.x*b.x + a.y*b.y + a.z*b.z + a.w*b.w;
}

// Multi-value warp reduce: lane l enters with v[0..31] (its partial for each of
// 32 outputs, index i = jsub*8+g); leaves with return = full sum for index l.
__device__ __forceinline__ float warp_multi_reduce32(float v[32], int l) {
    int cnt = 32;
    #pragma unroll
    for (int b = 4; b >= 0; b--) {
        const int o = 1 << b;
        const int half = cnt >> 1;
        const bool up = (l >> b) & 1;
        #pragma unroll
        for (int k = 0; k < 16; k++) {
            if (k < half) {
                float lo = v[k]        + __shfl_xor_sync(0xffffffffu, v[k], o);
                float hi = v[half + k] + __shfl_xor_sync(0xffffffffu, v[half + k], o);
                v[k] = up ? hi : lo;
            }
        }
        cnt = half;
    }
    return v[0];
}

// ---------------------------------------------------------------------------
// Kernel 1: split-K fused attention, shift-free softmax (exp(s-8)).
// grid = 2048: CTA (b, split) handles keys [split*100, split*100+100).
// Writes UNNORMALIZED e to out_attn, partial acc to g_ovp, exp-sum to g_psum.
// mlp kernel combines and normalizes.
// ---------------------------------------------------------------------------
__global__ __launch_bounds__(384, 3) void attn_kernel(
    const float* __restrict__ seq,
    const float* __restrict__ seq_e,
    const float* __restrict__ seq_t,
    const void* __restrict__ mask,
    const float* __restrict__ shared_attn,
    float* __restrict__ out_attn)   // = d_out + B*DN
{
    __shared__ __align__(16) float s_wk[MM];
    __shared__ __align__(16) float s_k[TT][MM];   // 36864 B tile buffer
    __shared__ float s_e[KH];                     // exp(s-8), local keys
    __shared__ float s_sum;
    __shared__ int   s_det[2];
    __shared__ unsigned char s_msk[KH];

    const int b  = blockIdx.x >> 1;
    const int bs = blockIdx.x & 1;
    const int K0 = bs * KH;
    const int t = threadIdx.x;
    const int w = t >> 5;
    const int l = t & 31;
    const size_t rowbase = (size_t)b * NN;

    // ---- init: wk to smem, mask dtype detection ----
    s_wk[t] = shared_attn[MM + t];
    if (t < 64) {
        unsigned int v = ((const unsigned int*)mask)[t];
        unsigned int bad = __ballot_sync(0xffffffffu, v > 1u);
        if (l == 0) s_det[w] = (bad != 0u);
    }
    __syncthreads();

    const bool mask_is_int = !(s_det[0] | s_det[1]);
    if (t < KH) {
        bool m = mask_is_int
            ? (((const int*)mask)[rowbase + K0 + t] != 0)
            : (((const unsigned char*)mask)[rowbase + K0 + t] != 0);
        s_msk[t] = m ? 1 : 0;
    }

    // wk into registers (lane-fixed chunks)
    float4 wa = ((const float4*)s_wk)[l];
    float4 we = ((const float4*)s_wk)[32 + l];
    float4 wc = ((const float4*)s_wk)[64 + l];
    __syncthreads();

    const float4* seq4  = (const float4*)seq;
    const float4* seqe4 = (const float4*)seq_e;
    const float4* seqt4 = (const float4*)seq_t;

    // staging registers for this warp's 2 rows
    float4 A0, E0, C0, A1, E1, C1;
    const int r0 = 2 * w, r1 = 2 * w + 1;

    // prologue: load tile 0 (all 24 rows valid; KH=100 > 24)
    {
        size_t o = (rowbase + K0 + r0) * 32 + l;
        A0 = seq4[o]; E0 = seqe4[o]; C0 = seqt4[o];
        o = (rowbase + K0 + r1) * 32 + l;
        A1 = seq4[o]; E1 = seqe4[o]; C1 = seqt4[o];
    }

    float acc = 0.0f;   // column t accumulator (unnormalized)

    for (int tt = 0; tt < NTI; tt++) {
        const int n0 = tt * TT;                       // local key offset
        const int Tc = (tt == NTI - 1) ? (KH - (NTI - 1) * TT) : TT;  // 4 last

        // ---- a: dot from registers, write exp weight, STS tile rows ----
        if (r0 < Tc) {
            float p = dot4(A0, wa) + dot4(E0, we) + dot4(C0, wc);
            #pragma unroll
            for (int o = 16; o; o >>= 1) p += __shfl_xor_sync(0xffffffffu, p, o);
            if (l == 0) s_e[n0 + r0] = s_msk[n0 + r0] ? 0.0f : __expf(p - 8.0f);
            float4* row = (float4*)s_k[r0];
            row[l] = A0; row[32 + l] = E0; row[64 + l] = C0;
        }
        if (r1 < Tc) {
            float p = dot4(A1, wa) + dot4(E1, we) + dot4(C1, wc);
            #pragma unroll
            for (int o = 16; o; o >>= 1) p += __shfl_xor_sync(0xffffffffu, p, o);
            if (l == 0) s_e[n0 + r1] = s_msk[n0 + r1] ? 0.0f : __expf(p - 8.0f);
            float4* row = (float4*)s_k[r1];
            row[l] = A1; row[32 + l] = E1; row[64 + l] = C1;
        }

        // ---- b: issue next tile's loads NOW (overlap accumulate) ----
        if (tt + 1 < NTI) {
            const int m0 = (tt + 1) * TT;
            int n = m0 + r0;
            if (n < KH) {
                size_t o = (rowbase + K0 + n) * 32 + l;
                A0 = seq4[o]; E0 = seqe4[o]; C0 = seqt4[o];
            }
            n = m0 + r1;
            if (n < KH) {
                size_t o = (rowbase + K0 + n) * 32 + l;
                A1 = seq4[o]; E1 = seqe4[o]; C1 = seqt4[o];
            }
        }
        __syncthreads();

        // ---- c: accumulate columns with raw exp weights ----
        float a = acc;
        if (Tc == TT) {
            #pragma unroll
            for (int i = 0; i < TT; i++) a = fmaf(s_e[n0 + i], s_k[i][t], a);
        } else {
            #pragma unroll
            for (int i = 0; i < 4; i++) a = fmaf(s_e[n0 + i], s_k[i][t], a);
        }
        acc = a;
        __syncthreads();
    }

    // ---- epilogue: partial sum of exps; write unnormalized outputs ----
    if (w == 0) {
        float s = 0.0f;
        #pragma unroll
        for (int k = l; k < KH; k += 32) s += s_e[k];
        #pragma unroll
        for (int o = 16; o; o >>= 1) s += __shfl_xor_sync(0xffffffffu, s, o);
        if (l == 0) { s_sum = s; g_psum[2 * b + bs] = s; }
    }
    __syncthreads();
    if (t < KH) out_attn[rowbase + K0 + t] = s_e[t];       // unnormalized
    g_ovp[(size_t)(2 * b + bs) * MM + t] = acc;            // unnormalized
}

// ---------------------------------------------------------------------------
// Kernel 2: combine split-K partials + FC + LN(residual q) + 2-layer MLP.
// G=8 batches per CTA (grid = 128), 256 threads (8 warps). (R5 matvec core.)
// ---------------------------------------------------------------------------
__global__ __launch_bounds__(256) void mlp_kernel(
    const float* __restrict__ src,
    const float* __restrict__ src_t,
    const float* __restrict__ fc_w,
    const float* __restrict__ ln_g,
    const float* __restrict__ ln_b,
    const float* __restrict__ w1,   // (256, 512)
    const float* __restrict__ w2,   // (128, 256)
    float* __restrict__ out,        // (B, 128)
    float* __restrict__ out_attn)   // (B, 200), unnormalized on entry
{
    __shared__ __align__(16) float s_ov[G][MM];
    __shared__ __align__(16) float s_q [G][SQ];
    __shared__ __align__(16) float s_x [G][SX];
    __shared__ __align__(16) float s_h [G][SH];
    __shared__ float s_inv[G];

    const int b0 = blockIdx.x * G;
    const int t  = threadIdx.x;
    const int w  = t >> 5;
    const int l  = t & 31;
    const int gl   = l & 7;   // lane's output batch after multi-reduce
    const int jsub = l >> 3;  // lane's output sub-row after multi-reduce

    // ---- Stage 0a: per-batch inverse softmax sums ----
    if (t < G) {
        float s = g_psum[2 * (b0 + t)] + g_psum[2 * (b0 + t) + 1];
        s_inv[t] = 1.0f / s;
    }
    __syncthreads();

    // ---- Stage 0b: combine ov partials, load q, src tail; normalize attn ----
    for (int i = t; i < G * MM; i += 256) {
        int g = i / MM, j = i - g * MM;
        float p0 = g_ovp[(size_t)(2 * (b0 + g)) * MM + j];
        float p1 = g_ovp[(size_t)(2 * (b0 + g) + 1) * MM + j];
        s_ov[g][j] = (p0 + p1) * s_inv[g];
        float qv;
        if (j < DNC)          qv = src[(size_t)(b0 + g) * DNC + j];
        else if (j < 2 * DNC) qv = 0.0f;
        else                  qv = src_t[(size_t)(b0 + g) * DTC + (j - 2 * DNC)];
        s_q[g][j] = qv;
    }
    for (int i = t; i < G * DNC; i += 256) {
        int g = i >> 7, j = i & 127;
        s_x[g][MM + j] = src[(size_t)(b0 + g) * DNC + j];
    }
    for (int i = t; i < G * NN; i += 256) {
        int g = i / NN, n = i - g * NN;
        out_attn[(size_t)(b0 + g) * NN + n] *= s_inv[g];
    }
    __syncthreads();

    // ---- Stage 1: y = ov @ fc_w.T + q  (384 rows; 96 quads over 8 warps) ----
    for (int q = w; q < 96; q += 8) {
        const float4* wr0 = (const float4*)(fc_w + (size_t)(4 * q + 0) * MM);
        const float4* wr1 = (const float4*)(fc_w + (size_t)(4 * q + 1) * MM);
        const float4* wr2 = (const float4*)(fc_w + (size_t)(4 * q + 2) * MM);
        const float4* wr3 = (const float4*)(fc_w + (size_t)(4 * q + 3) * MM);
        float acc[32];
        #pragma unroll
        for (int i = 0; i < 32; i++) acc[i] = 0.0f;
        #pragma unroll
        for (int c = 0; c < 3; c++) {
            float4 v0 = wr0[c*32+l], v1 = wr1[c*32+l], v2 = wr2[c*32+l], v3 = wr3[c*32+l];
            #pragma unroll
            for (int g = 0; g < G; g++) {
                float4 xv = ((const float4*)s_ov[g])[c*32+l];
                acc[g]      += dot4(v0, xv);
                acc[8 + g]  += dot4(v1, xv);
                acc[16 + g] += dot4(v2, xv);
                acc[24 + g] += dot4(v3, xv);
            }
        }
        float tot = warp_multi_reduce32(acc, l);
        int j = 4 * q + jsub;
        s_x[gl][j] = tot + s_q[gl][j];
    }
    __syncthreads();

    // ---- Stage 2: LayerNorm per batch row (warp g = batch g) ----
    {
        const int g = w;
        float vals[12];
        float smu = 0.0f;
        #pragma unroll
        for (int i = 0; i < 12; i++) { float x = s_x[g][l + 32*i]; vals[i] = x; smu += x; }
        #pragma unroll
        for (int o = 16; o; o >>= 1) smu += __shfl_xor_sync(0xffffffffu, smu, o);
        float mu = smu * (1.0f / MM);
        float sq = 0.0f;
        #pragma unroll
        for (int i = 0; i < 12; i++) { float d = vals[i] - mu; sq += d * d; }
        #pragma unroll
        for (int o = 16; o; o >>= 1) sq += __shfl_xor_sync(0xffffffffu, sq, o);
        float rstd = rsqrtf(sq * (1.0f / MM) + 1e-5f);
        #pragma unroll
        for (int i = 0; i < 12; i++) {
            int j = l + 32*i;
            s_x[g][j] = (vals[i] - mu) * rstd * ln_g[j] + ln_b[j];
        }
    }
    __syncthreads();

    // ---- Stage 3: h = relu(x @ w1.T)  (256 rows; 64 quads) ----
    for (int q = w; q < 64; q += 8) {
        const float4* wr0 = (const float4*)(w1 + (size_t)(4 * q + 0) * 512);
        const float4* wr1 = (const float4*)(w1 + (size_t)(4 * q + 1) * 512);
        const float4* wr2 = (const float4*)(w1 + (size_t)(4 * q + 2) * 512);
        const float4* wr3 = (const float4*)(w1 + (size_t)(4 * q + 3) * 512);
        float acc[32];
        #pragma unroll
        for (int i = 0; i < 32; i++) acc[i] = 0.0f;
        #pragma unroll
        for (int c = 0; c < 4; c++) {
            float4 v0 = wr0[c*32+l], v1 = wr1[c*32+l], v2 = wr2[c*32+l], v3 = wr3[c*32+l];
            #pragma unroll
            for (int g = 0; g < G; g++) {
                float4 xv = ((const float4*)s_x[g])[c*32+l];
                acc[g]      += dot4(v0, xv);
                acc[8 + g]  += dot4(v1, xv);
                acc[16 + g] += dot4(v2, xv);
                acc[24 + g] += dot4(v3, xv);
            }
        }
        float tot = warp_multi_reduce32(acc, l);
        s_h[gl][4 * q + jsub] = fmaxf(tot, 0.0f);
    }
    __syncthreads();

    // ---- Stage 4: o = h @ w2.T  (128 rows; 32 quads) -> global ----
    for (int q = w; q < 32; q += 8) {
        const float4* wr0 = (const float4*)(w2 + (size_t)(4 * q + 0) * 256);
        const float4* wr1 = (const float4*)(w2 + (size_t)(4 * q + 1) * 256);
        const float4* wr2 = (const float4*)(w2 + (size_t)(4 * q + 2) * 256);
        const float4* wr3 = (const float4*)(w2 + (size_t)(4 * q + 3) * 256);
        float acc[32];
        #pragma unroll
        for (int i = 0; i < 32; i++) acc[i] = 0.0f;
        #pragma unroll
        for (int c = 0; c < 2; c++) {
            float4 v0 = wr0[c*32+l], v1 = wr1[c*32+l], v2 = wr2[c*32+l], v3 = wr3[c*32+l];
            #pragma unroll
            for (int g = 0; g < G; g++) {
                float4 hv = ((const float4*)s_h[g])[c*32+l];
                acc[g]      += dot4(v0, hv);
                acc[8 + g]  += dot4(v1, hv);
                acc[16 + g] += dot4(v2, hv);
                acc[24 + g] += dot4(v3, hv);
            }
        }
        float tot = warp_multi_reduce32(acc, l);
        out[(size_t)(b0 + gl) * DNC + 4 * q + jsub] = tot;
    }
}

// ---------------------------------------------------------------------------
// Input order (setup_inputs dict order):
//   0 src (B,DN) f32          1 src_t (B,1,DT) f32      2 seq (B,N,DN) f32
//   3 seq_t (B,N,DT) f32      4 seq_e (B,N,DN) f32      5 mask (B,N) bool/int
//   6 shared_attn (1,2M) f32  7 fc_w (M,M) f32          8 ln_g (M,) f32
//   9 ln_b (M,) f32          10 agg_fc_w1 (256,512)    11 agg_fc_w2 (128,256)
// Output: out (B,128) then attn_w (B,200), concatenated f32.
// ---------------------------------------------------------------------------
extern "C" void kernel_launch(void* const* d_in, const int* in_sizes, int n_in,
                              void* d_out, int out_size) {
    const float* src         = (const float*)d_in[0];
    const float* src_t       = (const float*)d_in[1];
    const float* seq         = (const float*)d_in[2];
    const float* seq_t       = (const float*)d_in[3];
    const float* seq_e       = (const float*)d_in[4];
    const void*  msk         = d_in[5];
    const float* shared_attn = (const float*)d_in[6];
    const float* fc_w        = (const float*)d_in[7];
    const float* ln_g        = (const float*)d_in[8];
    const float* ln_b        = (const float*)d_in[9];
    const float* w1          = (const float*)d_in[10];
    const float* w2          = (const float*)d_in[11];
    float* out = (float*)d_out;
    float* out_attn = out + (size_t)BB * DNC;

    attn_kernel<<<2 * BB, 384>>>(seq, seq_e, seq_t, msk, shared_attn, out_attn);
    mlp_kernel<<<BB / G, 256>>>(src, src_t, fc_w, ln_g, ln_b, w1, w2,
                                out, out_attn);
}

// round 9
// speedup vs baseline: 1.7117x; 1.0540x over previous
#include <cuda_runtime.h>
#include <math.h>

// Problem constants
constexpr int BB  = 1024;
constexpr int NN  = 200;
constexpr int KH  = 100;   // keys per split CTA
constexpr int DNC = 128;   // DN
constexpr int DTC = 128;   // DT
constexpr int MM  = 384;   // DN + DN + DT
constexpr int G   = 4;     // batches per CTA in MLP kernel
constexpr int TT  = 24;    // rows per attention tile (2 per warp, 12 warps)
constexpr int NTI = 5;     // ceil(100/24); last tile has 4 rows

// padded smem strides (words) for conflict-free lane-scatter stores
constexpr int SQ = 388;    // s_q stride
constexpr int SX = 516;    // s_x stride
constexpr int SH = 260;    // s_h stride

// Scratch: split-K partial attention outputs and exp-sums
__device__ float g_ovp[2 * BB * MM];   // [b][split][m], unnormalized
__device__ float g_psum[2 * BB];       // [b][split] exp-sums

__device__ __forceinline__ float dot4(float4 a, float4 b) {
    return a.x*b.x + a.y*b.y + a.z*b.z + a.w*b.w;
}

// Multi-value warp reduce, 16 values: lane l enters with v[0..15] (partials for
// outputs i = jsub*4+g); leaves with return = full 32-lane sum for index (l&15).
__device__ __forceinline__ float warp_multi_reduce16(float v[16], int l) {
    #pragma unroll
    for (int k = 0; k < 16; k++) v[k] += __shfl_xor_sync(0xffffffffu, v[k], 16);
    int cnt = 16;
    #pragma unroll
    for (int b = 3; b >= 0; b--) {
        const int o = 1 << b;           // 8,4,2,1
        const int half = cnt >> 1;
        const bool up = (l >> b) & 1;
        #pragma unroll
        for (int k = 0; k < 8; k++) {
            if (k < half) {
                float lo = v[k]        + __shfl_xor_sync(0xffffffffu, v[k], o);
                float hi = v[half + k] + __shfl_xor_sync(0xffffffffu, v[half + k], o);
                v[k] = up ? hi : lo;
            }
        }
        cnt = half;
    }
    return v[0];
}

// ---------------------------------------------------------------------------
// Kernel 1: split-K fused attention, shift-free softmax (exp(s-8)). (R8 ver.)
// grid = 2048: CTA (b, split) handles keys [split*100, split*100+100).
// ---------------------------------------------------------------------------
__global__ __launch_bounds__(384, 3) void attn_kernel(
    const float* __restrict__ seq,
    const float* __restrict__ seq_e,
    const float* __restrict__ seq_t,
    const void* __restrict__ mask,
    const float* __restrict__ shared_attn,
    float* __restrict__ out_attn)   // = d_out + B*DN
{
    __shared__ __align__(16) float s_wk[MM];
    __shared__ __align__(16) float s_k[TT][MM];
    __shared__ float s_e[KH];
    __shared__ float s_sum;
    __shared__ int   s_det[2];
    __shared__ unsigned char s_msk[KH];

    const int b  = blockIdx.x >> 1;
    const int bs = blockIdx.x & 1;
    const int K0 = bs * KH;
    const int t = threadIdx.x;
    const int w = t >> 5;
    const int l = t & 31;
    const size_t rowbase = (size_t)b * NN;

    s_wk[t] = shared_attn[MM + t];
    if (t < 64) {
        unsigned int v = ((const unsigned int*)mask)[t];
        unsigned int bad = __ballot_sync(0xffffffffu, v > 1u);
        if (l == 0) s_det[w] = (bad != 0u);
    }
    __syncthreads();

    const bool mask_is_int = !(s_det[0] | s_det[1]);
    if (t < KH) {
        bool m = mask_is_int
            ? (((const int*)mask)[rowbase + K0 + t] != 0)
            : (((const unsigned char*)mask)[rowbase + K0 + t] != 0);
        s_msk[t] = m ? 1 : 0;
    }

    float4 wa = ((const float4*)s_wk)[l];
    float4 we = ((const float4*)s_wk)[32 + l];
    float4 wc = ((const float4*)s_wk)[64 + l];
    __syncthreads();

    const float4* seq4  = (const float4*)seq;
    const float4* seqe4 = (const float4*)seq_e;
    const float4* seqt4 = (const float4*)seq_t;

    float4 A0, E0, C0, A1, E1, C1;
    const int r0 = 2 * w, r1 = 2 * w + 1;
    {
        size_t o = (rowbase + K0 + r0) * 32 + l;
        A0 = seq4[o]; E0 = seqe4[o]; C0 = seqt4[o];
        o = (rowbase + K0 + r1) * 32 + l;
        A1 = seq4[o]; E1 = seqe4[o]; C1 = seqt4[o];
    }

    float acc = 0.0f;

    for (int tt = 0; tt < NTI; tt++) {
        const int n0 = tt * TT;
        const int Tc = (tt == NTI - 1) ? (KH - (NTI - 1) * TT) : TT;

        if (r0 < Tc) {
            float p = dot4(A0, wa) + dot4(E0, we) + dot4(C0, wc);
            #pragma unroll
            for (int o = 16; o; o >>= 1) p += __shfl_xor_sync(0xffffffffu, p, o);
            if (l == 0) s_e[n0 + r0] = s_msk[n0 + r0] ? 0.0f : __expf(p - 8.0f);
            float4* row = (float4*)s_k[r0];
            row[l] = A0; row[32 + l] = E0; row[64 + l] = C0;
        }
        if (r1 < Tc) {
            float p = dot4(A1, wa) + dot4(E1, we) + dot4(C1, wc);
            #pragma unroll
            for (int o = 16; o; o >>= 1) p += __shfl_xor_sync(0xffffffffu, p, o);
            if (l == 0) s_e[n0 + r1] = s_msk[n0 + r1] ? 0.0f : __expf(p - 8.0f);
            float4* row = (float4*)s_k[r1];
            row[l] = A1; row[32 + l] = E1; row[64 + l] = C1;
        }

        if (tt + 1 < NTI) {
            const int m0 = (tt + 1) * TT;
            int n = m0 + r0;
            if (n < KH) {
                size_t o = (rowbase + K0 + n) * 32 + l;
                A0 = seq4[o]; E0 = seqe4[o]; C0 = seqt4[o];
            }
            n = m0 + r1;
            if (n < KH) {
                size_t o = (rowbase + K0 + n) * 32 + l;
                A1 = seq4[o]; E1 = seqe4[o]; C1 = seqt4[o];
            }
        }
        __syncthreads();

        float a = acc;
        if (Tc == TT) {
            #pragma unroll
            for (int i = 0; i < TT; i++) a = fmaf(s_e[n0 + i], s_k[i][t], a);
        } else {
            #pragma unroll
            for (int i = 0; i < 4; i++) a = fmaf(s_e[n0 + i], s_k[i][t], a);
        }
        acc = a;
        __syncthreads();
    }

    if (w == 0) {
        float s = 0.0f;
        #pragma unroll
        for (int k = l; k < KH; k += 32) s += s_e[k];
        #pragma unroll
        for (int o = 16; o; o >>= 1) s += __shfl_xor_sync(0xffffffffu, s, o);
        if (l == 0) { s_sum = s; g_psum[2 * b + bs] = s; }
    }
    __syncthreads();
    if (t < KH) out_attn[rowbase + K0 + t] = s_e[t];       // unnormalized
    g_ovp[(size_t)(2 * b + bs) * MM + t] = acc;            // unnormalized
}

// ---------------------------------------------------------------------------
// Kernel 2: combine split-K partials + FC + LN(residual q) + 2-layer MLP.
// G=4 batches per CTA (grid = 256), 256 threads, 2 CTAs/SM (128-reg cap).
// J=4-quad matvec inner loop (as R5), 16 accumulators, reduce16.
// ---------------------------------------------------------------------------
__global__ __launch_bounds__(256, 2) void mlp_kernel(
    const float* __restrict__ src,
    const float* __restrict__ src_t,
    const float* __restrict__ fc_w,
    const float* __restrict__ ln_g,
    const float* __restrict__ ln_b,
    const float* __restrict__ w1,   // (256, 512)
    const float* __restrict__ w2,   // (128, 256)
    float* __restrict__ out,        // (B, 128)
    float* __restrict__ out_attn)   // (B, 200), unnormalized on entry
{
    __shared__ __align__(16) float s_ov[G][MM];
    __shared__ __align__(16) float s_q [G][SQ];
    __shared__ __align__(16) float s_x [G][SX];
    __shared__ __align__(16) float s_h [G][SH];
    __shared__ float s_inv[G];

    const int b0 = blockIdx.x * G;
    const int t  = threadIdx.x;
    const int w  = t >> 5;
    const int l  = t & 31;
    const int il   = l & 15;   // output index this lane owns after reduce16
    const int gl   = il & 3;   // output batch (G=4)
    const int jsub = il >> 2;  // output sub-row within the quad

    // ---- Stage 0a: per-batch inverse softmax sums ----
    if (t < G) {
        float s = g_psum[2 * (b0 + t)] + g_psum[2 * (b0 + t) + 1];
        s_inv[t] = 1.0f / s;
    }
    __syncthreads();

    // ---- Stage 0b: combine ov partials, load q, src tail; normalize attn ----
    for (int i = t; i < G * MM; i += 256) {
        int g = i / MM, j = i - g * MM;
        float p0 = g_ovp[(size_t)(2 * (b0 + g)) * MM + j];
        float p1 = g_ovp[(size_t)(2 * (b0 + g) + 1) * MM + j];
        s_ov[g][j] = (p0 + p1) * s_inv[g];
        float qv;
        if (j < DNC)          qv = src[(size_t)(b0 + g) * DNC + j];
        else if (j < 2 * DNC) qv = 0.0f;
        else                  qv = src_t[(size_t)(b0 + g) * DTC + (j - 2 * DNC)];
        s_q[g][j] = qv;
    }
    for (int i = t; i < G * DNC; i += 256) {
        int g = i >> 7, j = i & 127;
        s_x[g][MM + j] = src[(size_t)(b0 + g) * DNC + j];
    }
    for (int i = t; i < G * NN; i += 256) {
        int g = i / NN, n = i - g * NN;
        out_attn[(size_t)(b0 + g) * NN + n] *= s_inv[g];
    }
    __syncthreads();

    // ---- Stage 1: y = ov @ fc_w.T + q  (384 rows; 96 quads over 8 warps) ----
    for (int q = w; q < 96; q += 8) {
        const float4* wr0 = (const float4*)(fc_w + (size_t)(4 * q + 0) * MM);
        const float4* wr1 = (const float4*)(fc_w + (size_t)(4 * q + 1) * MM);
        const float4* wr2 = (const float4*)(fc_w + (size_t)(4 * q + 2) * MM);
        const float4* wr3 = (const float4*)(fc_w + (size_t)(4 * q + 3) * MM);
        float acc[16];
        #pragma unroll
        for (int i = 0; i < 16; i++) acc[i] = 0.0f;
        #pragma unroll
        for (int c = 0; c < 3; c++) {
            float4 v0 = wr0[c*32+l], v1 = wr1[c*32+l], v2 = wr2[c*32+l], v3 = wr3[c*32+l];
            #pragma unroll
            for (int g = 0; g < G; g++) {
                float4 xv = ((const float4*)s_ov[g])[c*32+l];
                acc[g]      += dot4(v0, xv);
                acc[4 + g]  += dot4(v1, xv);
                acc[8 + g]  += dot4(v2, xv);
                acc[12 + g] += dot4(v3, xv);
            }
        }
        float tot = warp_multi_reduce16(acc, l);
        if (l < 16) {
            int j = 4 * q + jsub;
            s_x[gl][j] = tot + s_q[gl][j];
        }
    }
    __syncthreads();

    // ---- Stage 2: LayerNorm per batch row (warps 0..3, warp g = batch g) ----
    if (w < G) {
        const int g = w;
        float vals[12];
        float smu = 0.0f;
        #pragma unroll
        for (int i = 0; i < 12; i++) { float x = s_x[g][l + 32*i]; vals[i] = x; smu += x; }
        #pragma unroll
        for (int o = 16; o; o >>= 1) smu += __shfl_xor_sync(0xffffffffu, smu, o);
        float mu = smu * (1.0f / MM);
        float sq = 0.0f;
        #pragma unroll
        for (int i = 0; i < 12; i++) { float d = vals[i] - mu; sq += d * d; }
        #pragma unroll
        for (int o = 16; o; o >>= 1) sq += __shfl_xor_sync(0xffffffffu, sq, o);
        float rstd = rsqrtf(sq * (1.0f / MM) + 1e-5f);
        #pragma unroll
        for (int i = 0; i < 12; i++) {
            int j = l + 32*i;
            s_x[g][j] = (vals[i] - mu) * rstd * ln_g[j] + ln_b[j];
        }
    }
    __syncthreads();

    // ---- Stage 3: h = relu(x @ w1.T)  (256 rows; 64 quads) ----
    for (int q = w; q < 64; q += 8) {
        const float4* wr0 = (const float4*)(w1 + (size_t)(4 * q + 0) * 512);
        const float4* wr1 = (const float4*)(w1 + (size_t)(4 * q + 1) * 512);
        const float4* wr2 = (const float4*)(w1 + (size_t)(4 * q + 2) * 512);
        const float4* wr3 = (const float4*)(w1 + (size_t)(4 * q + 3) * 512);
        float acc[16];
        #pragma unroll
        for (int i = 0; i < 16; i++) acc[i] = 0.0f;
        #pragma unroll
        for (int c = 0; c < 4; c++) {
            float4 v0 = wr0[c*32+l], v1 = wr1[c*32+l], v2 = wr2[c*32+l], v3 = wr3[c*32+l];
            #pragma unroll
            for (int g = 0; g < G; g++) {
                float4 xv = ((const float4*)s_x[g])[c*32+l];
                acc[g]      += dot4(v0, xv);
                acc[4 + g]  += dot4(v1, xv);
                acc[8 + g]  += dot4(v2, xv);
                acc[12 + g] += dot4(v3, xv);
            }
        }
        float tot = warp_multi_reduce16(acc, l);
        if (l < 16) s_h[gl][4 * q + jsub] = fmaxf(tot, 0.0f);
    }
    __syncthreads();

    // ---- Stage 4: o = h @ w2.T  (128 rows; 32 quads) -> global ----
    for (int q = w; q < 32; q += 8) {
        const float4* wr0 = (const float4*)(w2 + (size_t)(4 * q + 0) * 256);
        const float4* wr1 = (const float4*)(w2 + (size_t)(4 * q + 1) * 256);
        const float4* wr2 = (const float4*)(w2 + (size_t)(4 * q + 2) * 256);
        const float4* wr3 = (const float4*)(w2 + (size_t)(4 * q + 3) * 256);
        float acc[16];
        #pragma unroll
        for (int i = 0; i < 16; i++) acc[i] = 0.0f;
        #pragma unroll
        for (int c = 0; c < 2; c++) {
            float4 v0 = wr0[c*32+l], v1 = wr1[c*32+l], v2 = wr2[c*32+l], v3 = wr3[c*32+l];
            #pragma unroll
            for (int g = 0; g < G; g++) {
                float4 hv = ((const float4*)s_h[g])[c*32+l];
                acc[g]      += dot4(v0, hv);
                acc[4 + g]  += dot4(v1, hv);
                acc[8 + g]  += dot4(v2, hv);
                acc[12 + g] += dot4(v3, hv);
            }
        }
        float tot = warp_multi_reduce16(acc, l);
        if (l < 16) out[(size_t)(b0 + gl) * DNC + 4 * q + jsub] = tot;
    }
}

// ---------------------------------------------------------------------------
// Input order (setup_inputs dict order):
//   0 src (B,DN) f32          1 src_t (B,1,DT) f32      2 seq (B,N,DN) f32
//   3 seq_t (B,N,DT) f32      4 seq_e (B,N,DN) f32      5 mask (B,N) bool/int
//   6 shared_attn (1,2M) f32  7 fc_w (M,M) f32          8 ln_g (M,) f32
//   9 ln_b (M,) f32          10 agg_fc_w1 (256,512)    11 agg_fc_w2 (128,256)
// Output: out (B,128) then attn_w (B,200), concatenated f32.
// ---------------------------------------------------------------------------
extern "C" void kernel_launch(void* const* d_in, const int* in_sizes, int n_in,
                              void* d_out, int out_size) {
    const float* src         = (const float*)d_in[0];
    const float* src_t       = (const float*)d_in[1];
    const float* seq         = (const float*)d_in[2];
    const float* seq_t       = (const float*)d_in[3];
    const float* seq_e       = (const float*)d_in[4];
    const void*  msk         = d_in[5];
    const float* shared_attn = (const float*)d_in[6];
    const float* fc_w        = (const float*)d_in[7];
    const float* ln_g        = (const float*)d_in[8];
    const float* ln_b        = (const float*)d_in[9];
    const float* w1          = (const float*)d_in[10];
    const float* w2          = (const float*)d_in[11];
    float* out = (float*)d_out;
    float* out_attn = out + (size_t)BB * DNC;

    attn_kernel<<<2 * BB, 384>>>(seq, seq_e, seq_t, msk, shared_attn, out_attn);
    mlp_kernel<<<BB / G, 256>>>(src, src_t, fc_w, ln_g, ln_b, w1, w2,
                                out, out_attn);
}